// round 9
// baseline (speedup 1.0000x reference)
#include <cuda_runtime.h>
#include <cstdint>

// Embedding gather: out[i, :] = weight[indices[i], :]
// 819200 rows x 64 fp32 = 256B/row.
// v9: cp.async (LDGSTS) gather path. Register-held LDG MLP plateaued at
// ~74% DRAM across occ 40-83% (warps x MLP product constant => L1tex
// outstanding-miss cap). cp.async.cg 16B gathers carry no result registers
// and queue deeply: each block gathers 128 rows (2048 x 16B segs) into a
// 32KB smem tile, then streams it out as one contiguous coalesced store.
// Each thread stores exactly the segments it fetched -> no block barrier.

static constexpr int ROWS_PER_BLOCK  = 128;
static constexpr int THREADS         = 256;
static constexpr int SEGS            = ROWS_PER_BLOCK * 16;   // 16B segs per tile
static constexpr int SEGS_PER_THREAD = SEGS / THREADS;        // 8

__global__ __launch_bounds__(THREADS)
void embed_gather_cpasync(const int* __restrict__ indices,
                          const char* __restrict__ weight,
                          uint4* __restrict__ out)
{
    __shared__ __align__(16) uint4 tile[SEGS];   // 32KB

    const int       t        = threadIdx.x;
    const long long row_base = (long long)blockIdx.x * ROWS_PER_BLOCK;

    // Phase 1: 8 independent 16B async gathers per thread (no result regs).
#pragma unroll
    for (int k = 0; k < SEGS_PER_THREAD; k++) {
        const int s   = t + k * THREADS;     // segment within tile
        const int row = s >> 4;              // row within tile
        const int col = s & 15;              // 16B segment within row
        const int idx = __ldg(indices + row_base + row);
        const char* src = weight + ((long long)(unsigned)idx << 8) + (col << 4);
        const uint32_t dst = (uint32_t)__cvta_generic_to_shared(&tile[s]);
        asm volatile("cp.async.cg.shared.global [%0], [%1], 16;"
                     :: "r"(dst), "l"(src));
    }
    asm volatile("cp.async.commit_group;" ::: "memory");
    asm volatile("cp.async.wait_group 0;" ::: "memory");

    // Phase 2: contiguous streaming store of the whole 32KB tile.
    // Thread t owns the same segments it fetched; stores are warp-coalesced.
    uint4* dst_base = out + row_base * 16;
#pragma unroll
    for (int k = 0; k < SEGS_PER_THREAD; k++) {
        const int s = t + k * THREADS;
        uint4 v = tile[s];
        asm volatile("st.global.cs.v4.b32 [%0], {%1,%2,%3,%4};"
                     :: "l"(dst_base + s), "r"(v.x), "r"(v.y), "r"(v.z), "r"(v.w));
    }
}

// General fallback: 128-bit LDG, predicated (any shape).
__global__ __launch_bounds__(256)
void embed_gather_general(const int* __restrict__ indices,
                          const float4* __restrict__ weight,
                          float4* __restrict__ out,
                          long long total_vec)   // float4 count
{
    const long long stride = (long long)gridDim.x * blockDim.x;
    const long long base   = (long long)blockIdx.x * blockDim.x + threadIdx.x;

    for (long long p = base; p < total_vec; p += stride) {
        int idx = __ldg(indices + (p >> 4));
        float4 v = __ldg(weight + (long long)idx * 16 + (p & 15));
        __stcs(out + p, v);
    }
}

extern "C" void kernel_launch(void* const* d_in, const int* in_sizes, int n_in,
                              void* d_out, int out_size)
{
    const int* indices  = (const int*)d_in[0];     // 819200 int32
    long long  num_rows = in_sizes[0];

    if (num_rows % ROWS_PER_BLOCK == 0) {
        int blocks = (int)(num_rows / ROWS_PER_BLOCK);     // 6400
        embed_gather_cpasync<<<blocks, THREADS>>>(
            indices, (const char*)d_in[1], (uint4*)d_out);
    } else {
        long long total_vec = num_rows * 16;
        int blocks = (int)((total_vec + 1023) / 1024);
        embed_gather_general<<<blocks, 256>>>(
            indices, (const float4*)d_in[1], (float4*)d_out, total_vec);
    }
}